// round 9
// baseline (speedup 1.0000x reference)
#include <cuda_runtime.h>
#include <math.h>
#include <stdint.h>

#define NN   50000
#define EE   800000
#define IND  128
#define HIDD 256
#define OUTD 40
#define TOT  (EE + NN)
#define BN_EPS 1e-5f

// ---------------- scratch (device globals: alloc-guard compliant) ----------------
__device__ __align__(16) float g_t1[(size_t)NN * HIDD];
__device__ __align__(16) float g_t2[(size_t)NN * HIDD];
__device__ float g_dinv[NN];
__device__ int   g_deg[NN];
__device__ int   g_cnt[NN];
__device__ int   g_cur[NN];
__device__ int   g_off[NN + 1];
__device__ int   g_row[EE];
__device__ int   g_col[EE];
__device__ __align__(16) int   g_csr_col[TOT + 4];
__device__ __align__(16) float g_csr_w[TOT + 4];
__device__ float g_sum[HIDD];     // zero-init at load; bn_finalize re-zeroes after use
__device__ float g_sumsq[HIDD];
__device__ float g_bn_s[HIDD];
__device__ float g_bn_t[HIDD];

static inline int cdiv(int a, int b) { return (a + b - 1) / b; }

// ---------------- tf32 helpers ----------------
__device__ __forceinline__ float to_tf32(float x) {
    uint32_t u;
    asm("cvt.rna.tf32.f32 %0, %1;" : "=r"(u) : "f"(x));
    return __uint_as_float(u);
}

__device__ __forceinline__ void mma_tf32(float c[4], const uint32_t a[4], const uint32_t b[2]) {
    asm volatile(
        "mma.sync.aligned.m16n8k8.row.col.f32.tf32.tf32.f32 "
        "{%0,%1,%2,%3}, {%4,%5,%6,%7}, {%8,%9}, {%0,%1,%2,%3};\n"
        : "+f"(c[0]), "+f"(c[1]), "+f"(c[2]), "+f"(c[3])
        : "r"(a[0]), "r"(a[1]), "r"(a[2]), "r"(a[3]), "r"(b[0]), "r"(b[1]));
}

// ---------------- preprocessing (3 launches) ----------------
__global__ void k_convert_deg(const void* ei) {
    int e = blockIdx.x * blockDim.x + threadIdx.x;
    if (e >= EE) return;
    const unsigned long long* p8 = (const unsigned long long*)ei;
    bool is64 = true;
#pragma unroll
    for (int q = 0; q < 8; q++) is64 &= (p8[q] < (unsigned long long)NN);
    int r, c;
    if (is64) {
        const long long* p = (const long long*)ei;
        r = (int)p[e];
        c = (int)p[EE + e];
    } else {
        const int* p = (const int*)ei;
        r = p[e];
        c = p[EE + e];
    }
    g_row[e] = r;
    g_col[e] = c;
    atomicAdd(&g_deg[c], 1);
    atomicAdd(&g_cnt[r], 1);
}

__global__ void k_scan_dinv() {
    __shared__ int part[1024];
    int t = threadIdx.x;
    const int CH = (NN + 1023) / 1024;
    int b = t * CH;
    int e = min(NN, b + CH);
    int s = 0;
    for (int i = b; i < e; i++) {
        s += g_cnt[i] + 1;
        g_dinv[i] = rsqrtf((float)(g_deg[i] + 1));
        g_deg[i] = 0;
        g_cur[i] = 0;
    }
    part[t] = s;
    __syncthreads();
    for (int off = 1; off < 1024; off <<= 1) {
        int v = (t >= off) ? part[t - off] : 0;
        __syncthreads();
        part[t] += v;
        __syncthreads();
    }
    int pre = (t == 0) ? 0 : part[t - 1];
    for (int i = b; i < e; i++) {
        g_off[i] = pre;
        pre += g_cnt[i] + 1;
        g_cnt[i] = 0;
    }
    if (t == 1023) g_off[NN] = part[1023];
}

__global__ void k_fill() {
    int idx = blockIdx.x * blockDim.x + threadIdx.x;
    if (idx >= TOT) return;
    int r, c; float w;
    if (idx < EE) {
        r = g_row[idx];
        c = g_col[idx];
        w = g_dinv[r] * g_dinv[c];
    } else {
        r = idx - EE;
        c = r;
        float d = g_dinv[r];
        w = d * d;
    }
    int pos = g_off[r] + atomicAdd(&g_cur[r], 1);
    g_csr_col[pos] = c;
    g_csr_w[pos]   = w;
}

// ---------------- tensor-core GEMM, paired-smem layouts (LDS.64 reads) ----------------
template <bool FUSE, bool BIAS>
__global__ void __launch_bounds__(256) k_gemm_tc(
    const float* __restrict__ A, const float* __restrict__ B,
    const float* __restrict__ bias, float* __restrict__ C,
    int M, int K, int Ncols)
{
    constexpr int BM = 128, BN = 64, BK = 32;
    __shared__ float2 As2[BK * 68];
    __shared__ float2 Bs2[16 * 68];
    float* Af = (float*)As2;
    float* Bf = (float*)Bs2;

    const int tid  = threadIdx.x;
    const int warp = tid >> 5, lane = tid & 31;
    const int gid  = lane >> 2, tg = lane & 3;
    const int wm   = (warp & 3) * 32;
    const int wn   = (warp >> 2) * 32;
    const int bm   = blockIdx.y * BM, bn = blockIdx.x * BN;

    float c[2][4][4];
#pragma unroll
    for (int i = 0; i < 2; i++)
#pragma unroll
        for (int j = 0; j < 4; j++)
#pragma unroll
            for (int q = 0; q < 4; q++) c[i][j][q] = 0.f;

    float4 areg[4];
    float  breg[8];

#pragma unroll
    for (int r = 0; r < 4; r++) {
        int idx = tid + r * 256;
        int m = idx & 127, c4 = idx >> 7;
        int gm = bm + m;
        areg[r] = make_float4(0.f, 0.f, 0.f, 0.f);
        if (gm < M) areg[r] = *reinterpret_cast<const float4*>(A + (size_t)gm * K + c4 * 4);
    }
#pragma unroll
    for (int r = 0; r < 8; r++) {
        int idx = tid + r * 256;
        int kk = idx >> 6, n = idx & 63;
        breg[r] = (bn + n < Ncols) ? B[(size_t)kk * Ncols + bn + n] : 0.f;
    }

    for (int k0 = 0; k0 < K; k0 += BK) {
#pragma unroll
        for (int r = 0; r < 4; r++) {
            int idx = tid + r * 256;
            int m = idx & 127, c4 = idx >> 7;
            int mq = (m & 7) | ((m >> 4) << 3);
            int mslot = (m >> 3) & 1;
            float4 v = areg[r];
            if (FUSE) {
                int gk = k0 + c4 * 4;
                v.x = fmaxf(0.f, fmaf(v.x, g_bn_s[gk + 0], g_bn_t[gk + 0]));
                v.y = fmaxf(0.f, fmaf(v.y, g_bn_s[gk + 1], g_bn_t[gk + 1]));
                v.z = fmaxf(0.f, fmaf(v.z, g_bn_s[gk + 2], g_bn_t[gk + 2]));
                v.w = fmaxf(0.f, fmaf(v.w, g_bn_s[gk + 3], g_bn_t[gk + 3]));
            }
            int kb0 = c4 * 4;
            Af[((kb0 + 0) * 68 + mq) * 2 + mslot] = to_tf32(v.x);
            Af[((kb0 + 1) * 68 + mq) * 2 + mslot] = to_tf32(v.y);
            Af[((kb0 + 2) * 68 + mq) * 2 + mslot] = to_tf32(v.z);
            Af[((kb0 + 3) * 68 + mq) * 2 + mslot] = to_tf32(v.w);
        }
#pragma unroll
        for (int r = 0; r < 8; r++) {
            int idx = tid + r * 256;
            int kk = idx >> 6, n = idx & 63;
            int kq = (kk & 3) | ((kk >> 3) << 2);
            int kslot = (kk >> 2) & 1;
            Bf[(kq * 68 + n) * 2 + kslot] = to_tf32(breg[r]);
        }
        __syncthreads();

        if (k0 + BK < K) {
            int kn = k0 + BK;
#pragma unroll
            for (int r = 0; r < 4; r++) {
                int idx = tid + r * 256;
                int m = idx & 127, c4 = idx >> 7;
                int gm = bm + m;
                areg[r] = make_float4(0.f, 0.f, 0.f, 0.f);
                if (gm < M) areg[r] = *reinterpret_cast<const float4*>(A + (size_t)gm * K + kn + c4 * 4);
            }
#pragma unroll
            for (int r = 0; r < 8; r++) {
                int idx = tid + r * 256;
                int kk = idx >> 6, n = idx & 63;
                breg[r] = (bn + n < Ncols) ? B[(size_t)(kn + kk) * Ncols + bn + n] : 0.f;
            }
        }

#pragma unroll
        for (int kc = 0; kc < 4; kc++) {
            int kb = kc * 8 + tg;
            int kq = tg | (kc << 2);
            uint32_t a[2][4], b[4][2];
#pragma unroll
            for (int am = 0; am < 2; am++) {
                int mr = wm + am * 16 + gid;
                int mq = (mr & 7) | ((mr >> 4) << 3);
                float2 lo = As2[kb * 68 + mq];
                float2 hi = As2[(kb + 4) * 68 + mq];
                a[am][0] = __float_as_uint(lo.x);
                a[am][1] = __float_as_uint(lo.y);
                a[am][2] = __float_as_uint(hi.x);
                a[am][3] = __float_as_uint(hi.y);
            }
#pragma unroll
            for (int bi = 0; bi < 4; bi++) {
                int nc = wn + bi * 8 + gid;
                float2 pb = Bs2[kq * 68 + nc];
                b[bi][0] = __float_as_uint(pb.x);
                b[bi][1] = __float_as_uint(pb.y);
            }
#pragma unroll
            for (int am = 0; am < 2; am++)
#pragma unroll
                for (int bi = 0; bi < 4; bi++)
                    mma_tf32(c[am][bi], a[am], b[bi]);
        }
        __syncthreads();
    }

#pragma unroll
    for (int am = 0; am < 2; am++) {
#pragma unroll
        for (int bi = 0; bi < 4; bi++) {
            int row = bm + wm + am * 16 + gid;
            int col = bn + wn + bi * 8 + 2 * tg;
            float bv0 = 0.f, bv1 = 0.f;
            if (BIAS) {
                if (col < Ncols)     bv0 = bias[col];
                if (col + 1 < Ncols) bv1 = bias[col + 1];
            }
            if (row < M) {
                if (col < Ncols)     C[(size_t)row * Ncols + col]     = c[am][bi][0] + bv0;
                if (col + 1 < Ncols) C[(size_t)row * Ncols + col + 1] = c[am][bi][1] + bv1;
            }
            if (row + 8 < M) {
                if (col < Ncols)     C[(size_t)(row + 8) * Ncols + col]     = c[am][bi][2] + bv0;
                if (col + 1 < Ncols) C[(size_t)(row + 8) * Ncols + col + 1] = c[am][bi][3] + bv1;
            }
        }
    }
}

// ---------------- aggregation: multi-row blocks + vectorized CSR metadata ----------------
template <int F4, int RPB, bool BIAS>
__global__ void __launch_bounds__(F4 * RPB) k_agg_v(
    const float* __restrict__ h, const float* __restrict__ bias,
    float* __restrict__ out)
{
    const int F = F4 * 4;
    int i = blockIdx.x * RPB + threadIdx.x / F4;
    int t = threadIdx.x % F4;
    if (RPB > 1 && i >= NN) return;
    float4 acc = make_float4(0.f, 0.f, 0.f, 0.f);
    int p = g_off[i], end = g_off[i + 1];

    while (p < end && (p & 3)) {
        int   c0 = __ldg(&g_csr_col[p]);
        float w0 = __ldg(&g_csr_w[p]);
        float4 v0 = *reinterpret_cast<const float4*>(h + (size_t)c0 * F + t * 4);
        acc.x = fmaf(w0, v0.x, acc.x);
        acc.y = fmaf(w0, v0.y, acc.y);
        acc.z = fmaf(w0, v0.z, acc.z);
        acc.w = fmaf(w0, v0.w, acc.w);
        p++;
    }
    for (; p + 3 < end; p += 4) {
        int4   cv = *reinterpret_cast<const int4*>(&g_csr_col[p]);
        float4 wv = *reinterpret_cast<const float4*>(&g_csr_w[p]);
        float4 v0 = *reinterpret_cast<const float4*>(h + (size_t)cv.x * F + t * 4);
        float4 v1 = *reinterpret_cast<const float4*>(h + (size_t)cv.y * F + t * 4);
        float4 v2 = *reinterpret_cast<const float4*>(h + (size_t)cv.z * F + t * 4);
        float4 v3 = *reinterpret_cast<const float4*>(h + (size_t)cv.w * F + t * 4);
        acc.x = fmaf(wv.x, v0.x, fmaf(wv.y, v1.x, fmaf(wv.z, v2.x, fmaf(wv.w, v3.x, acc.x))));
        acc.y = fmaf(wv.x, v0.y, fmaf(wv.y, v1.y, fmaf(wv.z, v2.y, fmaf(wv.w, v3.y, acc.y))));
        acc.z = fmaf(wv.x, v0.z, fmaf(wv.y, v1.z, fmaf(wv.z, v2.z, fmaf(wv.w, v3.z, acc.z))));
        acc.w = fmaf(wv.x, v0.w, fmaf(wv.y, v1.w, fmaf(wv.z, v2.w, fmaf(wv.w, v3.w, acc.w))));
    }
    for (; p < end; p++) {
        int   c0 = __ldg(&g_csr_col[p]);
        float w0 = __ldg(&g_csr_w[p]);
        float4 v0 = *reinterpret_cast<const float4*>(h + (size_t)c0 * F + t * 4);
        acc.x = fmaf(w0, v0.x, acc.x);
        acc.y = fmaf(w0, v0.y, acc.y);
        acc.z = fmaf(w0, v0.z, acc.z);
        acc.w = fmaf(w0, v0.w, acc.w);
    }
    if (BIAS) {
        float4 b = *reinterpret_cast<const float4*>(bias + t * 4);
        acc.x += b.x; acc.y += b.y; acc.z += b.z; acc.w += b.w;
    }
    *reinterpret_cast<float4*>(out + (size_t)i * F + t * 4) = acc;
}

// ---------------- fused layer-3 agg + log_softmax (4 warps/block, warp per row) ----------------
__global__ void __launch_bounds__(128) k_agg_softmax(
    const float* __restrict__ h, const float* __restrict__ bias,
    float* __restrict__ out)
{
    int i = blockIdx.x * 4 + (threadIdx.x >> 5);
    int t = threadIdx.x & 31;
    if (i >= NN) return;
    float a0 = 0.f, a1 = 0.f;
    int p = g_off[i], end = g_off[i + 1];
    for (; p + 1 < end; p += 2) {
        int   c0 = __ldg(&g_csr_col[p]);
        int   c1 = __ldg(&g_csr_col[p + 1]);
        float w0 = __ldg(&g_csr_w[p]);
        float w1 = __ldg(&g_csr_w[p + 1]);
        const float* h0 = h + (size_t)c0 * OUTD;
        const float* h1 = h + (size_t)c1 * OUTD;
        a0 = fmaf(w0, h0[t], fmaf(w1, h1[t], a0));
        if (t < 8) a1 = fmaf(w0, h0[t + 32], fmaf(w1, h1[t + 32], a1));
    }
    if (p < end) {
        int   c0 = __ldg(&g_csr_col[p]);
        float w0 = __ldg(&g_csr_w[p]);
        const float* h0 = h + (size_t)c0 * OUTD;
        a0 = fmaf(w0, h0[t], a0);
        if (t < 8) a1 = fmaf(w0, h0[t + 32], a1);
    }
    float v0 = a0 + bias[t];
    float v1 = (t < 8) ? (a1 + bias[t + 32]) : -INFINITY;
    float m = fmaxf(v0, v1);
#pragma unroll
    for (int off = 16; off > 0; off >>= 1)
        m = fmaxf(m, __shfl_xor_sync(0xFFFFFFFFu, m, off));
    float s = expf(v0 - m) + ((t < 8) ? expf(v1 - m) : 0.f);
#pragma unroll
    for (int off = 16; off > 0; off >>= 1)
        s += __shfl_xor_sync(0xFFFFFFFFu, s, off);
    float l = m + logf(s);
    out[(size_t)i * OUTD + t] = v0 - l;
    if (t < 8) out[(size_t)i * OUTD + t + 32] = v1 - l;
}

// ---------------- batchnorm stats ----------------
__global__ void __launch_bounds__(256) k_stats(const float* __restrict__ h) {
    int c = threadIdx.x;
    int rows_per_block = (NN + gridDim.x - 1) / gridDim.x;
    int r0 = blockIdx.x * rows_per_block;
    int r1 = min(NN, r0 + rows_per_block);
    float s = 0.f, ss = 0.f;
    for (int r = r0; r < r1; r++) {
        float v = h[(size_t)r * HIDD + c];
        s += v;
        ss = fmaf(v, v, ss);
    }
    atomicAdd(&g_sum[c], s);
    atomicAdd(&g_sumsq[c], ss);
}

__global__ void k_bn_finalize(const float* __restrict__ gamma,
                              const float* __restrict__ beta) {
    int c = threadIdx.x;
    float mu = g_sum[c] * (1.f / NN);
    float var = g_sumsq[c] * (1.f / NN) - mu * mu;
    float rstd = rsqrtf(var + BN_EPS);
    float sc = rstd * gamma[c];
    g_bn_s[c] = sc;
    g_bn_t[c] = beta[c] - mu * sc;
    g_sum[c] = 0.f;
    g_sumsq[c] = 0.f;
}

// ---------------- launch ----------------
extern "C" void kernel_launch(void* const* d_in, const int* in_sizes, int n_in,
                              void* d_out, int out_size) {
    const float* x     = (const float*)d_in[0];
    const void*  ei    = d_in[1];
    const float* W1    = (const float*)d_in[2];
    const float* b1    = (const float*)d_in[3];
    const float* W2    = (const float*)d_in[4];
    const float* b2    = (const float*)d_in[5];
    const float* W3    = (const float*)d_in[6];
    const float* b3    = (const float*)d_in[7];
    const float* gamma = (const float*)d_in[8];
    const float* beta  = (const float*)d_in[9];
    float* out = (float*)d_out;

    float *t1, *t2;
    cudaGetSymbolAddress((void**)&t1, g_t1);
    cudaGetSymbolAddress((void**)&t2, g_t2);

    // preprocessing
    k_convert_deg<<<cdiv(EE, 256), 256>>>(ei);   // 0
    k_scan_dinv<<<1, 1024>>>();                  // 1
    k_fill<<<cdiv(TOT, 256), 256>>>();           // 2

    dim3 g256(4, cdiv(NN, 128));    // Ncols=256
    dim3 g40(1, cdiv(NN, 128));     // Ncols=40

    // layer 1: TRANSFORM-FIRST this round — puts the NEW paired-LDS GEMM at the
    // profiled slot (#3) with the exact shape round 6 measured (M=NN,K=128,N=256).
    k_gemm_tc<false, false><<<g256, 256>>>(x, W1, nullptr, t1, NN, IND, HIDD); // 3 <- profiled
    k_agg_v<64, 2, true><<<cdiv(NN, 2), 128>>>(t1, b1, t2);                    // 4
    k_stats<<<256, HIDD>>>(t2);                                                // 5
    k_bn_finalize<<<1, HIDD>>>(gamma, beta);                                   // 6

    // layer 2 (BN+ReLU fused into GEMM A-load), 256-wide agg 2 rows/block
    k_gemm_tc<true, false><<<g256, 256>>>(t2, W2, nullptr, t1, NN, HIDD, HIDD); // 7
    k_agg_v<64, 2, true><<<cdiv(NN, 2), 128>>>(t1, b2, t2);                     // 8
    k_stats<<<256, HIDD>>>(t2);                                                 // 9
    k_bn_finalize<<<1, HIDD>>>(gamma, beta);                                    // 10

    // layer 3: GEMM then fused agg+log_softmax straight to output
    k_gemm_tc<true, false><<<g40, 256>>>(t2, W3, nullptr, t1, NN, HIDD, OUTD);  // 11
    k_agg_softmax<<<cdiv(NN, 4), 128>>>(t1, b3, out);                           // 12
}

// round 10
// speedup vs baseline: 1.0502x; 1.0502x over previous
#include <cuda_runtime.h>
#include <cuda_bf16.h>
#include <math.h>
#include <stdint.h>

#define NN   50000
#define EE   800000
#define IND  128
#define HIDD 256
#define OUTD 40
#define TOT  (EE + NN)
#define BN_EPS 1e-5f

// ---------------- scratch (device globals: alloc-guard compliant) ----------------
__device__ __align__(16) float g_t1[(size_t)NN * HIDD];
__device__ __align__(16) float g_t2[(size_t)NN * HIDD];
__device__ float g_dinv[NN];
__device__ int   g_deg[NN];
__device__ int   g_cnt[NN];
__device__ int   g_cur[NN];
__device__ int   g_off[NN + 1];
__device__ int   g_row[EE];
__device__ int   g_col[EE];
__device__ __align__(16) int   g_csr_col[TOT + 4];
__device__ __align__(16) float g_csr_w[TOT + 4];
__device__ float g_sum[HIDD];     // zero-init at load; bn_finalize re-zeroes after use
__device__ float g_sumsq[HIDD];
__device__ float g_bn_s[HIDD];
__device__ float g_bn_t[HIDD];

static inline int cdiv(int a, int b) { return (a + b - 1) / b; }

// ---------------- bf16 helpers ----------------
__device__ __forceinline__ uint32_t pack_bf16(float lo, float hi) {
    uint32_t r;
    asm("cvt.rn.bf16x2.f32 %0, %1, %2;" : "=r"(r) : "f"(hi), "f"(lo));
    return r;   // low half = lo (k even), high half = hi (k odd)
}

__device__ __forceinline__ void mma_bf16(float c[4], const uint32_t a[4], const uint32_t b[2]) {
    asm volatile(
        "mma.sync.aligned.m16n8k16.row.col.f32.bf16.bf16.f32 "
        "{%0,%1,%2,%3}, {%4,%5,%6,%7}, {%8,%9}, {%0,%1,%2,%3};\n"
        : "+f"(c[0]), "+f"(c[1]), "+f"(c[2]), "+f"(c[3])
        : "r"(a[0]), "r"(a[1]), "r"(a[2]), "r"(a[3]), "r"(b[0]), "r"(b[1]));
}

// ---------------- preprocessing (3 launches) ----------------
__global__ void k_convert_deg(const void* ei) {
    int e = blockIdx.x * blockDim.x + threadIdx.x;
    if (e >= EE) return;
    const unsigned long long* p8 = (const unsigned long long*)ei;
    bool is64 = true;
#pragma unroll
    for (int q = 0; q < 8; q++) is64 &= (p8[q] < (unsigned long long)NN);
    int r, c;
    if (is64) {
        const long long* p = (const long long*)ei;
        r = (int)p[e];
        c = (int)p[EE + e];
    } else {
        const int* p = (const int*)ei;
        r = p[e];
        c = p[EE + e];
    }
    g_row[e] = r;
    g_col[e] = c;
    atomicAdd(&g_deg[c], 1);
    atomicAdd(&g_cnt[r], 1);
}

__global__ void k_scan_dinv() {
    __shared__ int part[1024];
    int t = threadIdx.x;
    const int CH = (NN + 1023) / 1024;
    int b = t * CH;
    int e = min(NN, b + CH);
    int s = 0;
    for (int i = b; i < e; i++) {
        s += g_cnt[i] + 1;
        g_dinv[i] = rsqrtf((float)(g_deg[i] + 1));
        g_deg[i] = 0;
        g_cur[i] = 0;
    }
    part[t] = s;
    __syncthreads();
    for (int off = 1; off < 1024; off <<= 1) {
        int v = (t >= off) ? part[t - off] : 0;
        __syncthreads();
        part[t] += v;
        __syncthreads();
    }
    int pre = (t == 0) ? 0 : part[t - 1];
    for (int i = b; i < e; i++) {
        g_off[i] = pre;
        pre += g_cnt[i] + 1;
        g_cnt[i] = 0;
    }
    if (t == 1023) g_off[NN] = part[1023];
}

__global__ void k_fill() {
    int idx = blockIdx.x * blockDim.x + threadIdx.x;
    if (idx >= TOT) return;
    int r, c; float w;
    if (idx < EE) {
        r = g_row[idx];
        c = g_col[idx];
        w = g_dinv[r] * g_dinv[c];
    } else {
        r = idx - EE;
        c = r;
        float d = g_dinv[r];
        w = d * d;
    }
    int pos = g_off[r] + atomicAdd(&g_cur[r], 1);
    g_csr_col[pos] = c;
    g_csr_w[pos]   = w;
}

// ---------------- tensor-core GEMM, bf16 m16n8k16 ----------------
// A smem: packed bf16x2 along k: As[k2][m], k2=k/2, row stride 136 (8 mod 32 -> conflict-free)
// B smem: packed bf16x2 along k: Bs[k2][n], row stride 72
template <bool FUSE, bool BIAS>
__global__ void __launch_bounds__(256) k_gemm_tc(
    const float* __restrict__ A, const float* __restrict__ B,
    const float* __restrict__ bias, float* __restrict__ C,
    int M, int K, int Ncols)
{
    constexpr int BM = 128, BN = 64, BK = 32;
    constexpr int ASTR = 136, BSTR = 72;
    __shared__ uint32_t As[16 * ASTR];   // 8704 B
    __shared__ uint32_t Bs[16 * BSTR];   // 4608 B

    const int tid  = threadIdx.x;
    const int warp = tid >> 5, lane = tid & 31;
    const int gid  = lane >> 2, tg = lane & 3;
    const int wm   = (warp & 3) * 32;
    const int wn   = (warp >> 2) * 32;
    const int bm   = blockIdx.y * BM, bn = blockIdx.x * BN;

    float c[2][4][4];
#pragma unroll
    for (int i = 0; i < 2; i++)
#pragma unroll
        for (int j = 0; j < 4; j++)
#pragma unroll
            for (int q = 0; q < 4; q++) c[i][j][q] = 0.f;

    float4 areg[4];      // A stage: (m, k c4*4..+3)
    float  breg[4][2];   // B stage: (k2, n) pairs: B[2k2][n], B[2k2+1][n]

    // prologue
#pragma unroll
    for (int r = 0; r < 4; r++) {
        int idx = tid + r * 256;
        int m = idx & 127, c4 = idx >> 7;
        int gm = bm + m;
        areg[r] = make_float4(0.f, 0.f, 0.f, 0.f);
        if (gm < M) areg[r] = *reinterpret_cast<const float4*>(A + (size_t)gm * K + c4 * 4);
    }
#pragma unroll
    for (int r = 0; r < 4; r++) {
        int idx = tid + r * 256;
        int k2 = idx >> 6, n = idx & 63;
        bool ok = (bn + n < Ncols);
        breg[r][0] = ok ? B[(size_t)(2 * k2 + 0) * Ncols + bn + n] : 0.f;
        breg[r][1] = ok ? B[(size_t)(2 * k2 + 1) * Ncols + bn + n] : 0.f;
    }

    for (int k0 = 0; k0 < K; k0 += BK) {
        // ---- store staged A (FUSE + bf16 pack) ----
#pragma unroll
        for (int r = 0; r < 4; r++) {
            int idx = tid + r * 256;
            int m = idx & 127, c4 = idx >> 7;
            float4 v = areg[r];
            if (FUSE) {
                int gk = k0 + c4 * 4;
                v.x = fmaxf(0.f, fmaf(v.x, g_bn_s[gk + 0], g_bn_t[gk + 0]));
                v.y = fmaxf(0.f, fmaf(v.y, g_bn_s[gk + 1], g_bn_t[gk + 1]));
                v.z = fmaxf(0.f, fmaf(v.z, g_bn_s[gk + 2], g_bn_t[gk + 2]));
                v.w = fmaxf(0.f, fmaf(v.w, g_bn_s[gk + 3], g_bn_t[gk + 3]));
            }
            As[(c4 * 2 + 0) * ASTR + m] = pack_bf16(v.x, v.y);
            As[(c4 * 2 + 1) * ASTR + m] = pack_bf16(v.z, v.w);
        }
        // ---- store staged B (bf16 pack) ----
#pragma unroll
        for (int r = 0; r < 4; r++) {
            int idx = tid + r * 256;
            int k2 = idx >> 6, n = idx & 63;
            Bs[k2 * BSTR + n] = pack_bf16(breg[r][0], breg[r][1]);
        }
        __syncthreads();

        // ---- prefetch next tile ----
        if (k0 + BK < K) {
            int kn = k0 + BK;
#pragma unroll
            for (int r = 0; r < 4; r++) {
                int idx = tid + r * 256;
                int m = idx & 127, c4 = idx >> 7;
                int gm = bm + m;
                areg[r] = make_float4(0.f, 0.f, 0.f, 0.f);
                if (gm < M) areg[r] = *reinterpret_cast<const float4*>(A + (size_t)gm * K + kn + c4 * 4);
            }
#pragma unroll
            for (int r = 0; r < 4; r++) {
                int idx = tid + r * 256;
                int k2 = idx >> 6, n = idx & 63;
                bool ok = (bn + n < Ncols);
                breg[r][0] = ok ? B[(size_t)(kn + 2 * k2 + 0) * Ncols + bn + n] : 0.f;
                breg[r][1] = ok ? B[(size_t)(kn + 2 * k2 + 1) * Ncols + bn + n] : 0.f;
            }
        }

        // ---- compute: 2 kc steps of k16 ----
#pragma unroll
        for (int kc = 0; kc < 2; kc++) {
            int kc8 = kc * 8;
            uint32_t a[2][4], b[4][2];
#pragma unroll
            for (int am = 0; am < 2; am++) {
                int mr = wm + am * 16 + gid;
                a[am][0] = As[(kc8 + tg) * ASTR + mr];
                a[am][1] = As[(kc8 + tg) * ASTR + mr + 8];
                a[am][2] = As[(kc8 + tg + 4) * ASTR + mr];
                a[am][3] = As[(kc8 + tg + 4) * ASTR + mr + 8];
            }
#pragma unroll
            for (int bi = 0; bi < 4; bi++) {
                int nc = wn + bi * 8 + gid;
                b[bi][0] = Bs[(kc8 + tg) * BSTR + nc];
                b[bi][1] = Bs[(kc8 + tg + 4) * BSTR + nc];
            }
#pragma unroll
            for (int am = 0; am < 2; am++)
#pragma unroll
                for (int bi = 0; bi < 4; bi++)
                    mma_bf16(c[am][bi], a[am], b[bi]);
        }
        __syncthreads();
    }

#pragma unroll
    for (int am = 0; am < 2; am++) {
#pragma unroll
        for (int bi = 0; bi < 4; bi++) {
            int row = bm + wm + am * 16 + gid;
            int col = bn + wn + bi * 8 + 2 * tg;
            float bv0 = 0.f, bv1 = 0.f;
            if (BIAS) {
                if (col < Ncols)     bv0 = bias[col];
                if (col + 1 < Ncols) bv1 = bias[col + 1];
            }
            if (row < M) {
                if (col < Ncols)     C[(size_t)row * Ncols + col]     = c[am][bi][0] + bv0;
                if (col + 1 < Ncols) C[(size_t)row * Ncols + col + 1] = c[am][bi][1] + bv1;
            }
            if (row + 8 < M) {
                if (col < Ncols)     C[(size_t)(row + 8) * Ncols + col]     = c[am][bi][2] + bv0;
                if (col + 1 < Ncols) C[(size_t)(row + 8) * Ncols + col + 1] = c[am][bi][3] + bv1;
            }
        }
    }
}

// ---------------- aggregation: multi-row blocks + vectorized CSR metadata ----------------
template <int F4, int RPB, bool BIAS>
__global__ void __launch_bounds__(F4 * RPB) k_agg_v(
    const float* __restrict__ h, const float* __restrict__ bias,
    float* __restrict__ out)
{
    const int F = F4 * 4;
    int i = blockIdx.x * RPB + threadIdx.x / F4;
    int t = threadIdx.x % F4;
    if (RPB > 1 && i >= NN) return;
    float4 acc = make_float4(0.f, 0.f, 0.f, 0.f);
    int p = g_off[i], end = g_off[i + 1];

    while (p < end && (p & 3)) {
        int   c0 = __ldg(&g_csr_col[p]);
        float w0 = __ldg(&g_csr_w[p]);
        float4 v0 = *reinterpret_cast<const float4*>(h + (size_t)c0 * F + t * 4);
        acc.x = fmaf(w0, v0.x, acc.x);
        acc.y = fmaf(w0, v0.y, acc.y);
        acc.z = fmaf(w0, v0.z, acc.z);
        acc.w = fmaf(w0, v0.w, acc.w);
        p++;
    }
    for (; p + 3 < end; p += 4) {
        int4   cv = *reinterpret_cast<const int4*>(&g_csr_col[p]);
        float4 wv = *reinterpret_cast<const float4*>(&g_csr_w[p]);
        float4 v0 = *reinterpret_cast<const float4*>(h + (size_t)cv.x * F + t * 4);
        float4 v1 = *reinterpret_cast<const float4*>(h + (size_t)cv.y * F + t * 4);
        float4 v2 = *reinterpret_cast<const float4*>(h + (size_t)cv.z * F + t * 4);
        float4 v3 = *reinterpret_cast<const float4*>(h + (size_t)cv.w * F + t * 4);
        acc.x = fmaf(wv.x, v0.x, fmaf(wv.y, v1.x, fmaf(wv.z, v2.x, fmaf(wv.w, v3.x, acc.x))));
        acc.y = fmaf(wv.x, v0.y, fmaf(wv.y, v1.y, fmaf(wv.z, v2.y, fmaf(wv.w, v3.y, acc.y))));
        acc.z = fmaf(wv.x, v0.z, fmaf(wv.y, v1.z, fmaf(wv.z, v2.z, fmaf(wv.w, v3.z, acc.z))));
        acc.w = fmaf(wv.x, v0.w, fmaf(wv.y, v1.w, fmaf(wv.z, v2.w, fmaf(wv.w, v3.w, acc.w))));
    }
    for (; p < end; p++) {
        int   c0 = __ldg(&g_csr_col[p]);
        float w0 = __ldg(&g_csr_w[p]);
        float4 v0 = *reinterpret_cast<const float4*>(h + (size_t)c0 * F + t * 4);
        acc.x = fmaf(w0, v0.x, acc.x);
        acc.y = fmaf(w0, v0.y, acc.y);
        acc.z = fmaf(w0, v0.z, acc.z);
        acc.w = fmaf(w0, v0.w, acc.w);
    }
    if (BIAS) {
        float4 b = *reinterpret_cast<const float4*>(bias + t * 4);
        acc.x += b.x; acc.y += b.y; acc.z += b.z; acc.w += b.w;
    }
    *reinterpret_cast<float4*>(out + (size_t)i * F + t * 4) = acc;
}

// ---------------- fused layer-3 agg + log_softmax (4 warps/block, warp per row) ----------------
__global__ void __launch_bounds__(128) k_agg_softmax(
    const float* __restrict__ h, const float* __restrict__ bias,
    float* __restrict__ out)
{
    int i = blockIdx.x * 4 + (threadIdx.x >> 5);
    int t = threadIdx.x & 31;
    if (i >= NN) return;
    float a0 = 0.f, a1 = 0.f;
    int p = g_off[i], end = g_off[i + 1];
    for (; p + 1 < end; p += 2) {
        int   c0 = __ldg(&g_csr_col[p]);
        int   c1 = __ldg(&g_csr_col[p + 1]);
        float w0 = __ldg(&g_csr_w[p]);
        float w1 = __ldg(&g_csr_w[p + 1]);
        const float* h0 = h + (size_t)c0 * OUTD;
        const float* h1 = h + (size_t)c1 * OUTD;
        a0 = fmaf(w0, h0[t], fmaf(w1, h1[t], a0));
        if (t < 8) a1 = fmaf(w0, h0[t + 32], fmaf(w1, h1[t + 32], a1));
    }
    if (p < end) {
        int   c0 = __ldg(&g_csr_col[p]);
        float w0 = __ldg(&g_csr_w[p]);
        const float* h0 = h + (size_t)c0 * OUTD;
        a0 = fmaf(w0, h0[t], a0);
        if (t < 8) a1 = fmaf(w0, h0[t + 32], a1);
    }
    float v0 = a0 + bias[t];
    float v1 = (t < 8) ? (a1 + bias[t + 32]) : -INFINITY;
    float m = fmaxf(v0, v1);
#pragma unroll
    for (int off = 16; off > 0; off >>= 1)
        m = fmaxf(m, __shfl_xor_sync(0xFFFFFFFFu, m, off));
    float s = expf(v0 - m) + ((t < 8) ? expf(v1 - m) : 0.f);
#pragma unroll
    for (int off = 16; off > 0; off >>= 1)
        s += __shfl_xor_sync(0xFFFFFFFFu, s, off);
    float l = m + logf(s);
    out[(size_t)i * OUTD + t] = v0 - l;
    if (t < 8) out[(size_t)i * OUTD + t + 32] = v1 - l;
}

// ---------------- batchnorm stats ----------------
__global__ void __launch_bounds__(256) k_stats(const float* __restrict__ h) {
    int c = threadIdx.x;
    int rows_per_block = (NN + gridDim.x - 1) / gridDim.x;
    int r0 = blockIdx.x * rows_per_block;
    int r1 = min(NN, r0 + rows_per_block);
    float s = 0.f, ss = 0.f;
    for (int r = r0; r < r1; r++) {
        float v = h[(size_t)r * HIDD + c];
        s += v;
        ss = fmaf(v, v, ss);
    }
    atomicAdd(&g_sum[c], s);
    atomicAdd(&g_sumsq[c], ss);
}

__global__ void k_bn_finalize(const float* __restrict__ gamma,
                              const float* __restrict__ beta) {
    int c = threadIdx.x;
    float mu = g_sum[c] * (1.f / NN);
    float var = g_sumsq[c] * (1.f / NN) - mu * mu;
    float rstd = rsqrtf(var + BN_EPS);
    float sc = rstd * gamma[c];
    g_bn_s[c] = sc;
    g_bn_t[c] = beta[c] - mu * sc;
    g_sum[c] = 0.f;
    g_sumsq[c] = 0.f;
}

// ---------------- launch ----------------
extern "C" void kernel_launch(void* const* d_in, const int* in_sizes, int n_in,
                              void* d_out, int out_size) {
    const float* x     = (const float*)d_in[0];
    const void*  ei    = d_in[1];
    const float* W1    = (const float*)d_in[2];
    const float* b1    = (const float*)d_in[3];
    const float* W2    = (const float*)d_in[4];
    const float* b2    = (const float*)d_in[5];
    const float* W3    = (const float*)d_in[6];
    const float* b3    = (const float*)d_in[7];
    const float* gamma = (const float*)d_in[8];
    const float* beta  = (const float*)d_in[9];
    float* out = (float*)d_out;

    float *t1, *t2;
    cudaGetSymbolAddress((void**)&t1, g_t1);
    cudaGetSymbolAddress((void**)&t2, g_t2);

    // preprocessing
    k_convert_deg<<<cdiv(EE, 256), 256>>>(ei);   // 0
    k_scan_dinv<<<1, 1024>>>();                  // 1
    k_fill<<<cdiv(TOT, 256), 256>>>();           // 2

    dim3 g256(4, cdiv(NN, 128));    // Ncols=256
    dim3 g40(1, cdiv(NN, 128));     // Ncols=40

    // layer 1: transform-first ONE more round — bf16 gemm1 at profiled slot 3,
    // exact same shape as rounds 6 (49.6us) and 9 (66.2us) for a clean A/B/C.
    k_gemm_tc<false, false><<<g256, 256>>>(x, W1, nullptr, t1, NN, IND, HIDD); // 3 <- profiled
    k_agg_v<64, 2, true><<<cdiv(NN, 2), 128>>>(t1, b1, t2);                    // 4
    k_stats<<<256, HIDD>>>(t2);                                                // 5
    k_bn_finalize<<<1, HIDD>>>(gamma, beta);                                   // 6

    // layer 2 (BN+ReLU fused into GEMM A-load)
    k_gemm_tc<true, false><<<g256, 256>>>(t2, W2, nullptr, t1, NN, HIDD, HIDD); // 7
    k_agg_v<64, 2, true><<<cdiv(NN, 2), 128>>>(t1, b2, t2);                     // 8
    k_stats<<<256, HIDD>>>(t2);                                                 // 9
    k_bn_finalize<<<1, HIDD>>>(gamma, beta);                                    // 10

    // layer 3: GEMM then fused agg+log_softmax straight to output
    k_gemm_tc<true, false><<<g40, 256>>>(t2, W3, nullptr, t1, NN, HIDD, OUTD);  // 11
    k_agg_softmax<<<cdiv(NN, 4), 128>>>(t1, b3, out);                           // 12
}

// round 11
// speedup vs baseline: 1.3076x; 1.2450x over previous
#include <cuda_runtime.h>
#include <cuda_bf16.h>
#include <math.h>
#include <stdint.h>

#define NN   50000
#define EE   800000
#define IND  128
#define HIDD 256
#define OUTD 40
#define TOT  (EE + NN)
#define BN_EPS 1e-5f

// ---------------- scratch (device globals: alloc-guard compliant) ----------------
__device__ __align__(16) float g_t1[(size_t)NN * HIDD];   // also aliased as bf16
__device__ __align__(16) float g_t2[(size_t)NN * HIDD];
__device__ float g_dinv[NN];
__device__ int   g_deg[NN];
__device__ int   g_cnt[NN];
__device__ int   g_cur[NN];
__device__ int   g_off[NN + 1];
__device__ int   g_row[EE];
__device__ int   g_col[EE];
__device__ __align__(16) int   g_csr_col[TOT + 4];
__device__ __align__(16) float g_csr_w[TOT + 4];
__device__ float g_sum[HIDD];     // zero-init at load; bn_finalize re-zeroes after use
__device__ float g_sumsq[HIDD];
__device__ float g_bn_s[HIDD];
__device__ float g_bn_t[HIDD];

static inline int cdiv(int a, int b) { return (a + b - 1) / b; }

// ---------------- tf32 helpers ----------------
__device__ __forceinline__ float to_tf32(float x) {
    uint32_t u;
    asm("cvt.rna.tf32.f32 %0, %1;" : "=r"(u) : "f"(x));
    return __uint_as_float(u);
}

__device__ __forceinline__ void mma_tf32(float c[4], const uint32_t a[4], const uint32_t b[2]) {
    asm volatile(
        "mma.sync.aligned.m16n8k8.row.col.f32.tf32.tf32.f32 "
        "{%0,%1,%2,%3}, {%4,%5,%6,%7}, {%8,%9}, {%0,%1,%2,%3};\n"
        : "+f"(c[0]), "+f"(c[1]), "+f"(c[2]), "+f"(c[3])
        : "r"(a[0]), "r"(a[1]), "r"(a[2]), "r"(a[3]), "r"(b[0]), "r"(b[1]));
}

// ---------------- preprocessing (3 launches) ----------------
__global__ void k_convert_deg(const void* ei) {
    int e = blockIdx.x * blockDim.x + threadIdx.x;
    if (e >= EE) return;
    const unsigned long long* p8 = (const unsigned long long*)ei;
    bool is64 = true;
#pragma unroll
    for (int q = 0; q < 8; q++) is64 &= (p8[q] < (unsigned long long)NN);
    int r, c;
    if (is64) {
        const long long* p = (const long long*)ei;
        r = (int)p[e];
        c = (int)p[EE + e];
    } else {
        const int* p = (const int*)ei;
        r = p[e];
        c = p[EE + e];
    }
    g_row[e] = r;
    g_col[e] = c;
    atomicAdd(&g_deg[c], 1);
    atomicAdd(&g_cnt[r], 1);
}

__global__ void k_scan_dinv() {
    __shared__ int part[1024];
    int t = threadIdx.x;
    const int CH = (NN + 1023) / 1024;
    int b = t * CH;
    int e = min(NN, b + CH);
    int s = 0;
    for (int i = b; i < e; i++) {
        s += g_cnt[i] + 1;
        g_dinv[i] = rsqrtf((float)(g_deg[i] + 1));
        g_deg[i] = 0;
        g_cur[i] = 0;
    }
    part[t] = s;
    __syncthreads();
    for (int off = 1; off < 1024; off <<= 1) {
        int v = (t >= off) ? part[t - off] : 0;
        __syncthreads();
        part[t] += v;
        __syncthreads();
    }
    int pre = (t == 0) ? 0 : part[t - 1];
    for (int i = b; i < e; i++) {
        g_off[i] = pre;
        pre += g_cnt[i] + 1;
        g_cnt[i] = 0;
    }
    if (t == 1023) g_off[NN] = part[1023];
}

__global__ void k_fill() {
    int idx = blockIdx.x * blockDim.x + threadIdx.x;
    if (idx >= TOT) return;
    int r, c; float w;
    if (idx < EE) {
        r = g_row[idx];
        c = g_col[idx];
        w = g_dinv[r] * g_dinv[c];
    } else {
        r = idx - EE;
        c = r;
        float d = g_dinv[r];
        w = d * d;
    }
    int pos = g_off[r] + atomicAdd(&g_cur[r], 1);
    g_csr_col[pos] = c;
    g_csr_w[pos]   = w;
}

// ---------------- tensor-core GEMM (round-6 proven tf32 layout) ----------------
// BF16OUT: epilogue stores bf16x2 pairs into C reinterpreted as __nv_bfloat16*.
template <bool FUSE, bool BIAS, bool BF16OUT>
__global__ void __launch_bounds__(256) k_gemm_tc(
    const float* __restrict__ A, const float* __restrict__ B,
    const float* __restrict__ bias, float* __restrict__ C,
    int M, int K, int Ncols)
{
    constexpr int BM = 128, BN = 64, BK = 32;
    constexpr int ASTR = 36, BSTR = 68;
    __shared__ float As[BM * ASTR];
    __shared__ float Bs[BK * BSTR];

    const int tid  = threadIdx.x;
    const int warp = tid >> 5, lane = tid & 31;
    const int gid  = lane >> 2, tg = lane & 3;
    const int wm   = (warp & 3) * 32;
    const int wn   = (warp >> 2) * 32;
    const int bm   = blockIdx.y * BM, bn = blockIdx.x * BN;

    float c[2][4][4];
#pragma unroll
    for (int i = 0; i < 2; i++)
#pragma unroll
        for (int j = 0; j < 4; j++)
#pragma unroll
            for (int q = 0; q < 4; q++) c[i][j][q] = 0.f;

    float4 areg[4];
    float  breg[8];

#pragma unroll
    for (int r = 0; r < 4; r++) {
        int idx = tid + r * 256;
        int m = idx >> 3, c4 = idx & 7;
        int gm = bm + m;
        areg[r] = make_float4(0.f, 0.f, 0.f, 0.f);
        if (gm < M) areg[r] = *reinterpret_cast<const float4*>(A + (size_t)gm * K + c4 * 4);
    }
#pragma unroll
    for (int r = 0; r < 8; r++) {
        int idx = tid + r * 256;
        int kk = idx >> 6, n = idx & 63;
        breg[r] = (bn + n < Ncols) ? B[(size_t)kk * Ncols + bn + n] : 0.f;
    }

    for (int k0 = 0; k0 < K; k0 += BK) {
#pragma unroll
        for (int r = 0; r < 4; r++) {
            int idx = tid + r * 256;
            int m = idx >> 3, c4 = idx & 7;
            float4 v = areg[r];
            if (FUSE) {
                int gk = k0 + c4 * 4;
                v.x = fmaxf(0.f, fmaf(v.x, g_bn_s[gk + 0], g_bn_t[gk + 0]));
                v.y = fmaxf(0.f, fmaf(v.y, g_bn_s[gk + 1], g_bn_t[gk + 1]));
                v.z = fmaxf(0.f, fmaf(v.z, g_bn_s[gk + 2], g_bn_t[gk + 2]));
                v.w = fmaxf(0.f, fmaf(v.w, g_bn_s[gk + 3], g_bn_t[gk + 3]));
            }
            As[(c4 * 4 + 0) * 0 + m * ASTR + c4 * 4 + 0] = 0.f; // placeholder removed below
        }
        // NOTE: the placeholder line above is logically dead; real stores follow.
#pragma unroll
        for (int r = 0; r < 4; r++) {
            int idx = tid + r * 256;
            int m = idx >> 3, c4 = idx & 7;
            float4 v = areg[r];
            if (FUSE) {
                int gk = k0 + c4 * 4;
                v.x = fmaxf(0.f, fmaf(v.x, g_bn_s[gk + 0], g_bn_t[gk + 0]));
                v.y = fmaxf(0.f, fmaf(v.y, g_bn_s[gk + 1], g_bn_t[gk + 1]));
                v.z = fmaxf(0.f, fmaf(v.z, g_bn_s[gk + 2], g_bn_t[gk + 2]));
                v.w = fmaxf(0.f, fmaf(v.w, g_bn_s[gk + 3], g_bn_t[gk + 3]));
            }
            *reinterpret_cast<float4*>(&As[m * ASTR + c4 * 4]) =
                make_float4(to_tf32(v.x), to_tf32(v.y), to_tf32(v.z), to_tf32(v.w));
        }
#pragma unroll
        for (int r = 0; r < 8; r++) {
            int idx = tid + r * 256;
            int kk = idx >> 6, n = idx & 63;
            Bs[kk * BSTR + n] = to_tf32(breg[r]);
        }
        __syncthreads();

        if (k0 + BK < K) {
            int kn = k0 + BK;
#pragma unroll
            for (int r = 0; r < 4; r++) {
                int idx = tid + r * 256;
                int m = idx >> 3, c4 = idx & 7;
                int gm = bm + m;
                areg[r] = make_float4(0.f, 0.f, 0.f, 0.f);
                if (gm < M) areg[r] = *reinterpret_cast<const float4*>(A + (size_t)gm * K + kn + c4 * 4);
            }
#pragma unroll
            for (int r = 0; r < 8; r++) {
                int idx = tid + r * 256;
                int kk = idx >> 6, n = idx & 63;
                breg[r] = (bn + n < Ncols) ? B[(size_t)(kn + kk) * Ncols + bn + n] : 0.f;
            }
        }

#pragma unroll
        for (int kc = 0; kc < 4; kc++) {
            int kb = kc * 8 + tg;
            uint32_t a[2][4], b[4][2];
#pragma unroll
            for (int am = 0; am < 2; am++) {
                int mr = wm + am * 16 + gid;
                a[am][0] = __float_as_uint(As[mr * ASTR + kb]);
                a[am][1] = __float_as_uint(As[(mr + 8) * ASTR + kb]);
                a[am][2] = __float_as_uint(As[mr * ASTR + kb + 4]);
                a[am][3] = __float_as_uint(As[(mr + 8) * ASTR + kb + 4]);
            }
#pragma unroll
            for (int bi = 0; bi < 4; bi++) {
                int nc = wn + bi * 8 + gid;
                b[bi][0] = __float_as_uint(Bs[kb * BSTR + nc]);
                b[bi][1] = __float_as_uint(Bs[(kb + 4) * BSTR + nc]);
            }
#pragma unroll
            for (int am = 0; am < 2; am++)
#pragma unroll
                for (int bi = 0; bi < 4; bi++)
                    mma_tf32(c[am][bi], a[am], b[bi]);
        }
        __syncthreads();
    }

#pragma unroll
    for (int am = 0; am < 2; am++) {
#pragma unroll
        for (int bi = 0; bi < 4; bi++) {
            int row = bm + wm + am * 16 + gid;
            int col = bn + wn + bi * 8 + 2 * tg;
            float bv0 = 0.f, bv1 = 0.f;
            if (BIAS) {
                if (col < Ncols)     bv0 = bias[col];
                if (col + 1 < Ncols) bv1 = bias[col + 1];
            }
            if (BF16OUT) {
                __nv_bfloat16* Cb = reinterpret_cast<__nv_bfloat16*>(C);
                if (row < M && col < Ncols)
                    *reinterpret_cast<__nv_bfloat162*>(Cb + (size_t)row * Ncols + col) =
                        __floats2bfloat162_rn(c[am][bi][0] + bv0, c[am][bi][1] + bv1);
                if (row + 8 < M && col < Ncols)
                    *reinterpret_cast<__nv_bfloat162*>(Cb + (size_t)(row + 8) * Ncols + col) =
                        __floats2bfloat162_rn(c[am][bi][2] + bv0, c[am][bi][3] + bv1);
            } else {
                if (row < M) {
                    if (col < Ncols)     C[(size_t)row * Ncols + col]     = c[am][bi][0] + bv0;
                    if (col + 1 < Ncols) C[(size_t)row * Ncols + col + 1] = c[am][bi][1] + bv1;
                }
                if (row + 8 < M) {
                    if (col < Ncols)     C[(size_t)(row + 8) * Ncols + col]     = c[am][bi][2] + bv0;
                    if (col + 1 < Ncols) C[(size_t)(row + 8) * Ncols + col + 1] = c[am][bi][3] + bv1;
                }
            }
        }
    }
}

// ---------------- fp32 aggregation (layer 1): multi-row blocks + vectorized CSR ----------------
template <int F4, int RPB, bool BIAS>
__global__ void __launch_bounds__(F4 * RPB) k_agg_v(
    const float* __restrict__ h, const float* __restrict__ bias,
    float* __restrict__ out)
{
    const int F = F4 * 4;
    int i = blockIdx.x * RPB + threadIdx.x / F4;
    int t = threadIdx.x % F4;
    if (RPB > 1 && i >= NN) return;
    float4 acc = make_float4(0.f, 0.f, 0.f, 0.f);
    int p = g_off[i], end = g_off[i + 1];

    while (p < end && (p & 3)) {
        int   c0 = __ldg(&g_csr_col[p]);
        float w0 = __ldg(&g_csr_w[p]);
        float4 v0 = *reinterpret_cast<const float4*>(h + (size_t)c0 * F + t * 4);
        acc.x = fmaf(w0, v0.x, acc.x);
        acc.y = fmaf(w0, v0.y, acc.y);
        acc.z = fmaf(w0, v0.z, acc.z);
        acc.w = fmaf(w0, v0.w, acc.w);
        p++;
    }
    for (; p + 3 < end; p += 4) {
        int4   cv = *reinterpret_cast<const int4*>(&g_csr_col[p]);
        float4 wv = *reinterpret_cast<const float4*>(&g_csr_w[p]);
        float4 v0 = *reinterpret_cast<const float4*>(h + (size_t)cv.x * F + t * 4);
        float4 v1 = *reinterpret_cast<const float4*>(h + (size_t)cv.y * F + t * 4);
        float4 v2 = *reinterpret_cast<const float4*>(h + (size_t)cv.z * F + t * 4);
        float4 v3 = *reinterpret_cast<const float4*>(h + (size_t)cv.w * F + t * 4);
        acc.x = fmaf(wv.x, v0.x, fmaf(wv.y, v1.x, fmaf(wv.z, v2.x, fmaf(wv.w, v3.x, acc.x))));
        acc.y = fmaf(wv.x, v0.y, fmaf(wv.y, v1.y, fmaf(wv.z, v2.y, fmaf(wv.w, v3.y, acc.y))));
        acc.z = fmaf(wv.x, v0.z, fmaf(wv.y, v1.z, fmaf(wv.z, v2.z, fmaf(wv.w, v3.z, acc.z))));
        acc.w = fmaf(wv.x, v0.w, fmaf(wv.y, v1.w, fmaf(wv.z, v2.w, fmaf(wv.w, v3.w, acc.w))));
    }
    for (; p < end; p++) {
        int   c0 = __ldg(&g_csr_col[p]);
        float w0 = __ldg(&g_csr_w[p]);
        float4 v0 = *reinterpret_cast<const float4*>(h + (size_t)c0 * F + t * 4);
        acc.x = fmaf(w0, v0.x, acc.x);
        acc.y = fmaf(w0, v0.y, acc.y);
        acc.z = fmaf(w0, v0.z, acc.z);
        acc.w = fmaf(w0, v0.w, acc.w);
    }
    if (BIAS) {
        float4 b = *reinterpret_cast<const float4*>(bias + t * 4);
        acc.x += b.x; acc.y += b.y; acc.z += b.z; acc.w += b.w;
    }
    *reinterpret_cast<float4*>(out + (size_t)i * F + t * 4) = acc;
}

// ---------------- bf16 aggregation (layer 2): gather bf16, fp32 accumulate ----------------
// 32 lanes per row, each owning 8 features (uint4 = 8 bf16 per gather).
template <int RPB>
__global__ void __launch_bounds__(32 * RPB) k_agg_bf16(
    const __nv_bfloat16* __restrict__ h, const float* __restrict__ bias,
    float* __restrict__ out)
{
    int i = blockIdx.x * RPB + threadIdx.x / 32;
    int t = threadIdx.x % 32;
    if (i >= NN) return;
    float acc[8] = {0.f, 0.f, 0.f, 0.f, 0.f, 0.f, 0.f, 0.f};
    int p = g_off[i], end = g_off[i + 1];

#define GATHER_BF(cc, ww)                                                          \
    {                                                                              \
        uint4 v = *reinterpret_cast<const uint4*>(h + (size_t)(cc) * HIDD + t * 8);\
        const uint32_t* pv = &v.x;                                                 \
        _Pragma("unroll")                                                          \
        for (int j = 0; j < 4; j++) {                                              \
            float2 f = __bfloat1622float2(                                         \
                *reinterpret_cast<const __nv_bfloat162*>(&pv[j]));                 \
            acc[2 * j]     = fmaf((ww), f.x, acc[2 * j]);                          \
            acc[2 * j + 1] = fmaf((ww), f.y, acc[2 * j + 1]);                      \
        }                                                                          \
    }

    while (p < end && (p & 3)) {
        GATHER_BF(__ldg(&g_csr_col[p]), __ldg(&g_csr_w[p]));
        p++;
    }
    for (; p + 3 < end; p += 4) {
        int4   cv = *reinterpret_cast<const int4*>(&g_csr_col[p]);
        float4 wv = *reinterpret_cast<const float4*>(&g_csr_w[p]);
        GATHER_BF(cv.x, wv.x);
        GATHER_BF(cv.y, wv.y);
        GATHER_BF(cv.z, wv.z);
        GATHER_BF(cv.w, wv.w);
    }
    for (; p < end; p++) {
        GATHER_BF(__ldg(&g_csr_col[p]), __ldg(&g_csr_w[p]));
    }
#undef GATHER_BF

    float4 b0 = *reinterpret_cast<const float4*>(bias + t * 8);
    float4 b1 = *reinterpret_cast<const float4*>(bias + t * 8 + 4);
    float4 o0 = make_float4(acc[0] + b0.x, acc[1] + b0.y, acc[2] + b0.z, acc[3] + b0.w);
    float4 o1 = make_float4(acc[4] + b1.x, acc[5] + b1.y, acc[6] + b1.z, acc[7] + b1.w);
    *reinterpret_cast<float4*>(out + (size_t)i * HIDD + t * 8)     = o0;
    *reinterpret_cast<float4*>(out + (size_t)i * HIDD + t * 8 + 4) = o1;
}

// ---------------- fused layer-3 agg + log_softmax (4 warps/block, warp per row) ----------------
__global__ void __launch_bounds__(128) k_agg_softmax(
    const float* __restrict__ h, const float* __restrict__ bias,
    float* __restrict__ out)
{
    int i = blockIdx.x * 4 + (threadIdx.x >> 5);
    int t = threadIdx.x & 31;
    if (i >= NN) return;
    float a0 = 0.f, a1 = 0.f;
    int p = g_off[i], end = g_off[i + 1];
    for (; p + 1 < end; p += 2) {
        int   c0 = __ldg(&g_csr_col[p]);
        int   c1 = __ldg(&g_csr_col[p + 1]);
        float w0 = __ldg(&g_csr_w[p]);
        float w1 = __ldg(&g_csr_w[p + 1]);
        const float* h0 = h + (size_t)c0 * OUTD;
        const float* h1 = h + (size_t)c1 * OUTD;
        a0 = fmaf(w0, h0[t], fmaf(w1, h1[t], a0));
        if (t < 8) a1 = fmaf(w0, h0[t + 32], fmaf(w1, h1[t + 32], a1));
    }
    if (p < end) {
        int   c0 = __ldg(&g_csr_col[p]);
        float w0 = __ldg(&g_csr_w[p]);
        const float* h0 = h + (size_t)c0 * OUTD;
        a0 = fmaf(w0, h0[t], a0);
        if (t < 8) a1 = fmaf(w0, h0[t + 32], a1);
    }
    float v0 = a0 + bias[t];
    float v1 = (t < 8) ? (a1 + bias[t + 32]) : -INFINITY;
    float m = fmaxf(v0, v1);
#pragma unroll
    for (int off = 16; off > 0; off >>= 1)
        m = fmaxf(m, __shfl_xor_sync(0xFFFFFFFFu, m, off));
    float s = expf(v0 - m) + ((t < 8) ? expf(v1 - m) : 0.f);
#pragma unroll
    for (int off = 16; off > 0; off >>= 1)
        s += __shfl_xor_sync(0xFFFFFFFFu, s, off);
    float l = m + logf(s);
    out[(size_t)i * OUTD + t] = v0 - l;
    if (t < 8) out[(size_t)i * OUTD + t + 32] = v1 - l;
}

// ---------------- batchnorm stats ----------------
__global__ void __launch_bounds__(256) k_stats(const float* __restrict__ h) {
    int c = threadIdx.x;
    int rows_per_block = (NN + gridDim.x - 1) / gridDim.x;
    int r0 = blockIdx.x * rows_per_block;
    int r1 = min(NN, r0 + rows_per_block);
    float s = 0.f, ss = 0.f;
    for (int r = r0; r < r1; r++) {
        float v = h[(size_t)r * HIDD + c];
        s += v;
        ss = fmaf(v, v, ss);
    }
    atomicAdd(&g_sum[c], s);
    atomicAdd(&g_sumsq[c], ss);
}

__global__ void k_bn_finalize(const float* __restrict__ gamma,
                              const float* __restrict__ beta) {
    int c = threadIdx.x;
    float mu = g_sum[c] * (1.f / NN);
    float var = g_sumsq[c] * (1.f / NN) - mu * mu;
    float rstd = rsqrtf(var + BN_EPS);
    float sc = rstd * gamma[c];
    g_bn_s[c] = sc;
    g_bn_t[c] = beta[c] - mu * sc;
    g_sum[c] = 0.f;
    g_sumsq[c] = 0.f;
}

// ---------------- launch ----------------
extern "C" void kernel_launch(void* const* d_in, const int* in_sizes, int n_in,
                              void* d_out, int out_size) {
    const float* x     = (const float*)d_in[0];
    const void*  ei    = d_in[1];
    const float* W1    = (const float*)d_in[2];
    const float* b1    = (const float*)d_in[3];
    const float* W2    = (const float*)d_in[4];
    const float* b2    = (const float*)d_in[5];
    const float* W3    = (const float*)d_in[6];
    const float* b3    = (const float*)d_in[7];
    const float* gamma = (const float*)d_in[8];
    const float* beta  = (const float*)d_in[9];
    float* out = (float*)d_out;

    float *t1, *t2;
    cudaGetSymbolAddress((void**)&t1, g_t1);
    cudaGetSymbolAddress((void**)&t2, g_t2);
    __nv_bfloat16* t1b = reinterpret_cast<__nv_bfloat16*>(t1);

    // preprocessing
    k_convert_deg<<<cdiv(EE, 256), 256>>>(ei);   // 0
    k_scan_dinv<<<1, 1024>>>();                  // 1
    k_fill<<<cdiv(TOT, 256), 256>>>();           // 2

    dim3 g256(4, cdiv(NN, 128));    // Ncols=256
    dim3 g40(1, cdiv(NN, 128));     // Ncols=40

    // layer 1: agg-first (fp32, 128-wide, 4 rows/block), GEMM fp32-out with fused bias
    k_agg_v<32, 4, false><<<cdiv(NN, 4), 128>>>(x, nullptr, t1);                  // 3
    k_gemm_tc<false, true, false><<<g256, 256>>>(t1, W1, b1, t2, NN, IND, HIDD);  // 4
    k_stats<<<256, HIDD>>>(t2);                                                   // 5
    k_bn_finalize<<<1, HIDD>>>(gamma, beta);                                      // 6

    // layer 2: GEMM (BN+ReLU fused in) writes BF16; agg gathers bf16 -> fp32 t2
    k_gemm_tc<true, false, true><<<g256, 256>>>(t2, W2, nullptr, t1, NN, HIDD, HIDD); // 7
    k_agg_bf16<4><<<cdiv(NN, 4), 128>>>(t1b, b2, t2);                                 // 8
    k_stats<<<256, HIDD>>>(t2);                                                        // 9
    k_bn_finalize<<<1, HIDD>>>(gamma, beta);                                           // 10

    // layer 3: GEMM fp32-out then fused agg+log_softmax straight to output
    k_gemm_tc<true, false, false><<<g40, 256>>>(t2, W3, nullptr, t1, NN, HIDD, OUTD);  // 11
    k_agg_softmax<<<cdiv(NN, 4), 128>>>(t1, b3, out);                                  // 12
}

// round 12
// speedup vs baseline: 1.3175x; 1.0076x over previous
#include <cuda_runtime.h>
#include <cuda_bf16.h>
#include <math.h>
#include <stdint.h>

#define NN   50000
#define EE   800000
#define IND  128
#define HIDD 256
#define OUTD 40
#define TOT  (EE + NN)
#define XQ   (NN * IND / 4)     // x quads for bf16 cast
#define BN_EPS 1e-5f

// ---------------- scratch (device globals: alloc-guard compliant) ----------------
__device__ __align__(16) float g_t1[(size_t)NN * HIDD];   // fp32 / bf16 aliased
__device__ __align__(16) float g_t2[(size_t)NN * HIDD];
__device__ __align__(16) __nv_bfloat16 g_xb[(size_t)NN * IND];
__device__ float g_dinv[NN];
__device__ int   g_deg[NN];
__device__ int   g_cnt[NN];
__device__ int   g_cur[NN];
__device__ int   g_off[NN + 1];
__device__ int   g_row[EE];
__device__ int   g_col[EE];
__device__ __align__(16) int   g_csr_col[TOT + 4];
__device__ __align__(16) float g_csr_w[TOT + 4];
__device__ float g_sum[HIDD];     // zero-init at load; bn_finalize re-zeroes after use
__device__ float g_sumsq[HIDD];
__device__ float g_bn_s[HIDD];
__device__ float g_bn_t[HIDD];

static inline int cdiv(int a, int b) { return (a + b - 1) / b; }

// ---------------- tf32 helpers ----------------
__device__ __forceinline__ float to_tf32(float x) {
    uint32_t u;
    asm("cvt.rna.tf32.f32 %0, %1;" : "=r"(u) : "f"(x));
    return __uint_as_float(u);
}

__device__ __forceinline__ void mma_tf32(float c[4], const uint32_t a[4], const uint32_t b[2]) {
    asm volatile(
        "mma.sync.aligned.m16n8k8.row.col.f32.tf32.tf32.f32 "
        "{%0,%1,%2,%3}, {%4,%5,%6,%7}, {%8,%9}, {%0,%1,%2,%3};\n"
        : "+f"(c[0]), "+f"(c[1]), "+f"(c[2]), "+f"(c[3])
        : "r"(a[0]), "r"(a[1]), "r"(a[2]), "r"(a[3]), "r"(b[0]), "r"(b[1]));
}

// ---------------- preprocessing ----------------
// Fused: edge convert + degree count (idx < EE) AND x -> bf16 cast (idx < XQ).
__global__ void k_convert_deg_xcast(const void* ei, const float* __restrict__ x) {
    int idx = blockIdx.x * blockDim.x + threadIdx.x;
    if (idx < XQ) {
        float4 v = *reinterpret_cast<const float4*>(x + (size_t)idx * 4);
        __nv_bfloat162 a = __floats2bfloat162_rn(v.x, v.y);
        __nv_bfloat162 b = __floats2bfloat162_rn(v.z, v.w);
        uint2 u = make_uint2(*reinterpret_cast<uint32_t*>(&a),
                             *reinterpret_cast<uint32_t*>(&b));
        *reinterpret_cast<uint2*>(g_xb + (size_t)idx * 4) = u;
    }
    if (idx >= EE) return;
    const unsigned long long* p8 = (const unsigned long long*)ei;
    bool is64 = true;
#pragma unroll
    for (int q = 0; q < 8; q++) is64 &= (p8[q] < (unsigned long long)NN);
    int r, c;
    if (is64) {
        const long long* p = (const long long*)ei;
        r = (int)p[idx];
        c = (int)p[EE + idx];
    } else {
        const int* p = (const int*)ei;
        r = p[idx];
        c = p[EE + idx];
    }
    g_row[idx] = r;
    g_col[idx] = c;
    atomicAdd(&g_deg[c], 1);
    atomicAdd(&g_cnt[r], 1);
}

__global__ void k_scan_dinv() {
    __shared__ int part[1024];
    int t = threadIdx.x;
    const int CH = (NN + 1023) / 1024;
    int b = t * CH;
    int e = min(NN, b + CH);
    int s = 0;
    for (int i = b; i < e; i++) {
        s += g_cnt[i] + 1;
        g_dinv[i] = rsqrtf((float)(g_deg[i] + 1));
        g_deg[i] = 0;
        g_cur[i] = 0;
    }
    part[t] = s;
    __syncthreads();
    for (int off = 1; off < 1024; off <<= 1) {
        int v = (t >= off) ? part[t - off] : 0;
        __syncthreads();
        part[t] += v;
        __syncthreads();
    }
    int pre = (t == 0) ? 0 : part[t - 1];
    for (int i = b; i < e; i++) {
        g_off[i] = pre;
        pre += g_cnt[i] + 1;
        g_cnt[i] = 0;
    }
    if (t == 1023) g_off[NN] = part[1023];
}

__global__ void k_fill() {
    int idx = blockIdx.x * blockDim.x + threadIdx.x;
    if (idx >= TOT) return;
    int r, c; float w;
    if (idx < EE) {
        r = g_row[idx];
        c = g_col[idx];
        w = g_dinv[r] * g_dinv[c];
    } else {
        r = idx - EE;
        c = r;
        float d = g_dinv[r];
        w = d * d;
    }
    int pos = g_off[r] + atomicAdd(&g_cur[r], 1);
    g_csr_col[pos] = c;
    g_csr_w[pos]   = w;
}

// ---------------- tensor-core GEMM (round-6 proven tf32 layout, clean) ----------------
template <bool FUSE, bool BIAS, bool BF16OUT>
__global__ void __launch_bounds__(256) k_gemm_tc(
    const float* __restrict__ A, const float* __restrict__ B,
    const float* __restrict__ bias, float* __restrict__ C,
    int M, int K, int Ncols)
{
    constexpr int BM = 128, BN = 64, BK = 32;
    constexpr int ASTR = 36, BSTR = 68;
    __shared__ float As[BM * ASTR];
    __shared__ float Bs[BK * BSTR];

    const int tid  = threadIdx.x;
    const int warp = tid >> 5, lane = tid & 31;
    const int gid  = lane >> 2, tg = lane & 3;
    const int wm   = (warp & 3) * 32;
    const int wn   = (warp >> 2) * 32;
    const int bm   = blockIdx.y * BM, bn = blockIdx.x * BN;

    float c[2][4][4];
#pragma unroll
    for (int i = 0; i < 2; i++)
#pragma unroll
        for (int j = 0; j < 4; j++)
#pragma unroll
            for (int q = 0; q < 4; q++) c[i][j][q] = 0.f;

    float4 areg[4];
    float  breg[8];

#pragma unroll
    for (int r = 0; r < 4; r++) {
        int idx = tid + r * 256;
        int m = idx >> 3, c4 = idx & 7;
        int gm = bm + m;
        areg[r] = make_float4(0.f, 0.f, 0.f, 0.f);
        if (gm < M) areg[r] = *reinterpret_cast<const float4*>(A + (size_t)gm * K + c4 * 4);
    }
#pragma unroll
    for (int r = 0; r < 8; r++) {
        int idx = tid + r * 256;
        int kk = idx >> 6, n = idx & 63;
        breg[r] = (bn + n < Ncols) ? B[(size_t)kk * Ncols + bn + n] : 0.f;
    }

    for (int k0 = 0; k0 < K; k0 += BK) {
#pragma unroll
        for (int r = 0; r < 4; r++) {
            int idx = tid + r * 256;
            int m = idx >> 3, c4 = idx & 7;
            float4 v = areg[r];
            if (FUSE) {
                int gk = k0 + c4 * 4;
                v.x = fmaxf(0.f, fmaf(v.x, g_bn_s[gk + 0], g_bn_t[gk + 0]));
                v.y = fmaxf(0.f, fmaf(v.y, g_bn_s[gk + 1], g_bn_t[gk + 1]));
                v.z = fmaxf(0.f, fmaf(v.z, g_bn_s[gk + 2], g_bn_t[gk + 2]));
                v.w = fmaxf(0.f, fmaf(v.w, g_bn_s[gk + 3], g_bn_t[gk + 3]));
            }
            *reinterpret_cast<float4*>(&As[m * ASTR + c4 * 4]) =
                make_float4(to_tf32(v.x), to_tf32(v.y), to_tf32(v.z), to_tf32(v.w));
        }
#pragma unroll
        for (int r = 0; r < 8; r++) {
            int idx = tid + r * 256;
            int kk = idx >> 6, n = idx & 63;
            Bs[kk * BSTR + n] = to_tf32(breg[r]);
        }
        __syncthreads();

        if (k0 + BK < K) {
            int kn = k0 + BK;
#pragma unroll
            for (int r = 0; r < 4; r++) {
                int idx = tid + r * 256;
                int m = idx >> 3, c4 = idx & 7;
                int gm = bm + m;
                areg[r] = make_float4(0.f, 0.f, 0.f, 0.f);
                if (gm < M) areg[r] = *reinterpret_cast<const float4*>(A + (size_t)gm * K + kn + c4 * 4);
            }
#pragma unroll
            for (int r = 0; r < 8; r++) {
                int idx = tid + r * 256;
                int kk = idx >> 6, n = idx & 63;
                breg[r] = (bn + n < Ncols) ? B[(size_t)(kn + kk) * Ncols + bn + n] : 0.f;
            }
        }

#pragma unroll
        for (int kc = 0; kc < 4; kc++) {
            int kb = kc * 8 + tg;
            uint32_t a[2][4], b[4][2];
#pragma unroll
            for (int am = 0; am < 2; am++) {
                int mr = wm + am * 16 + gid;
                a[am][0] = __float_as_uint(As[mr * ASTR + kb]);
                a[am][1] = __float_as_uint(As[(mr + 8) * ASTR + kb]);
                a[am][2] = __float_as_uint(As[mr * ASTR + kb + 4]);
                a[am][3] = __float_as_uint(As[(mr + 8) * ASTR + kb + 4]);
            }
#pragma unroll
            for (int bi = 0; bi < 4; bi++) {
                int nc = wn + bi * 8 + gid;
                b[bi][0] = __float_as_uint(Bs[kb * BSTR + nc]);
                b[bi][1] = __float_as_uint(Bs[(kb + 4) * BSTR + nc]);
            }
#pragma unroll
            for (int am = 0; am < 2; am++)
#pragma unroll
                for (int bi = 0; bi < 4; bi++)
                    mma_tf32(c[am][bi], a[am], b[bi]);
        }
        __syncthreads();
    }

#pragma unroll
    for (int am = 0; am < 2; am++) {
#pragma unroll
        for (int bi = 0; bi < 4; bi++) {
            int row = bm + wm + am * 16 + gid;
            int col = bn + wn + bi * 8 + 2 * tg;
            float bv0 = 0.f, bv1 = 0.f;
            if (BIAS) {
                if (col < Ncols)     bv0 = bias[col];
                if (col + 1 < Ncols) bv1 = bias[col + 1];
            }
            if (BF16OUT) {
                __nv_bfloat16* Cb = reinterpret_cast<__nv_bfloat16*>(C);
                if (row < M && col < Ncols)
                    *reinterpret_cast<__nv_bfloat162*>(Cb + (size_t)row * Ncols + col) =
                        __floats2bfloat162_rn(c[am][bi][0] + bv0, c[am][bi][1] + bv1);
                if (row + 8 < M && col < Ncols)
                    *reinterpret_cast<__nv_bfloat162*>(Cb + (size_t)(row + 8) * Ncols + col) =
                        __floats2bfloat162_rn(c[am][bi][2] + bv0, c[am][bi][3] + bv1);
            } else {
                if (row < M) {
                    if (col < Ncols)     C[(size_t)row * Ncols + col]     = c[am][bi][0] + bv0;
                    if (col + 1 < Ncols) C[(size_t)row * Ncols + col + 1] = c[am][bi][1] + bv1;
                }
                if (row + 8 < M) {
                    if (col < Ncols)     C[(size_t)(row + 8) * Ncols + col]     = c[am][bi][2] + bv0;
                    if (col + 1 < Ncols) C[(size_t)(row + 8) * Ncols + col + 1] = c[am][bi][3] + bv1;
                }
            }
        }
    }
}

// ---------------- bf16 aggregation: gather bf16, fp32 accumulate, fp32 out ----------------
// F features per row; 32 lanes per row, V = F/32 bf16 per lane.
template <int F, int RPB, bool BIAS>
__global__ void __launch_bounds__(32 * RPB) k_agg_bf16(
    const __nv_bfloat16* __restrict__ h, const float* __restrict__ bias,
    float* __restrict__ out)
{
    constexpr int V = F / 32;     // 4 (F=128) or 8 (F=256)
    constexpr int V2 = V / 2;     // uint32 words per gather
    int i = blockIdx.x * RPB + threadIdx.x / 32;
    int t = threadIdx.x % 32;
    if (i >= NN) return;
    float acc[V];
#pragma unroll
    for (int j = 0; j < V; j++) acc[j] = 0.f;
    int p = g_off[i], end = g_off[i + 1];

#define GATHER_BF(cc, ww)                                                           \
    {                                                                               \
        uint32_t wreg[V2];                                                          \
        const __nv_bfloat16* src = h + (size_t)(cc) * F + t * V;                    \
        if constexpr (V2 == 2) {                                                    \
            uint2 u = *reinterpret_cast<const uint2*>(src);                         \
            wreg[0] = u.x; wreg[1] = u.y;                                           \
        } else {                                                                    \
            uint4 u = *reinterpret_cast<const uint4*>(src);                         \
            wreg[0] = u.x; wreg[1] = u.y; wreg[2] = u.z; wreg[3] = u.w;             \
        }                                                                           \
        _Pragma("unroll")                                                           \
        for (int j = 0; j < V2; j++) {                                              \
            float2 f = __bfloat1622float2(                                          \
                *reinterpret_cast<const __nv_bfloat162*>(&wreg[j]));                \
            acc[2 * j]     = fmaf((ww), f.x, acc[2 * j]);                           \
            acc[2 * j + 1] = fmaf((ww), f.y, acc[2 * j + 1]);                       \
        }                                                                           \
    }

    while (p < end && (p & 3)) {
        GATHER_BF(__ldg(&g_csr_col[p]), __ldg(&g_csr_w[p]));
        p++;
    }
    for (; p + 3 < end; p += 4) {
        int4   cv = *reinterpret_cast<const int4*>(&g_csr_col[p]);
        float4 wv = *reinterpret_cast<const float4*>(&g_csr_w[p]);
        GATHER_BF(cv.x, wv.x);
        GATHER_BF(cv.y, wv.y);
        GATHER_BF(cv.z, wv.z);
        GATHER_BF(cv.w, wv.w);
    }
    for (; p < end; p++) {
        GATHER_BF(__ldg(&g_csr_col[p]), __ldg(&g_csr_w[p]));
    }
#undef GATHER_BF

#pragma unroll
    for (int v4 = 0; v4 < V / 4; v4++) {
        float4 o;
        o.x = acc[v4 * 4 + 0];
        o.y = acc[v4 * 4 + 1];
        o.z = acc[v4 * 4 + 2];
        o.w = acc[v4 * 4 + 3];
        if (BIAS) {
            float4 b = *reinterpret_cast<const float4*>(bias + t * V + v4 * 4);
            o.x += b.x; o.y += b.y; o.z += b.z; o.w += b.w;
        }
        *reinterpret_cast<float4*>(out + (size_t)i * F + t * V + v4 * 4) = o;
    }
}

// ---------------- fused layer-3 bf16 agg + log_softmax (warp per row) ----------------
// h is bf16 [N, 40]; lane t<20 owns classes (2t, 2t+1) via one bf16x2 load.
__global__ void __launch_bounds__(128) k_agg_softmax_bf16(
    const __nv_bfloat16* __restrict__ h, const float* __restrict__ bias,
    float* __restrict__ out)
{
    int i = blockIdx.x * 4 + (threadIdx.x >> 5);
    int t = threadIdx.x & 31;
    if (i >= NN) return;
    float a0 = 0.f, a1 = 0.f;
    int p = g_off[i], end = g_off[i + 1];
    bool act = (t < OUTD / 2);
    for (; p + 1 < end; p += 2) {
        int   c0 = __ldg(&g_csr_col[p]);
        int   c1 = __ldg(&g_csr_col[p + 1]);
        float w0 = __ldg(&g_csr_w[p]);
        float w1 = __ldg(&g_csr_w[p + 1]);
        if (act) {
            float2 f0 = __bfloat1622float2(
                *reinterpret_cast<const __nv_bfloat162*>(h + (size_t)c0 * OUTD + 2 * t));
            float2 f1 = __bfloat1622float2(
                *reinterpret_cast<const __nv_bfloat162*>(h + (size_t)c1 * OUTD + 2 * t));
            a0 = fmaf(w0, f0.x, fmaf(w1, f1.x, a0));
            a1 = fmaf(w0, f0.y, fmaf(w1, f1.y, a1));
        }
    }
    if (p < end && act) {
        int   c0 = __ldg(&g_csr_col[p]);
        float w0 = __ldg(&g_csr_w[p]);
        float2 f0 = __bfloat1622float2(
            *reinterpret_cast<const __nv_bfloat162*>(h + (size_t)c0 * OUTD + 2 * t));
        a0 = fmaf(w0, f0.x, a0);
        a1 = fmaf(w0, f0.y, a1);
    }
    float v0 = act ? (a0 + bias[2 * t])     : -INFINITY;
    float v1 = act ? (a1 + bias[2 * t + 1]) : -INFINITY;
    float m = fmaxf(v0, v1);
#pragma unroll
    for (int off = 16; off > 0; off >>= 1)
        m = fmaxf(m, __shfl_xor_sync(0xFFFFFFFFu, m, off));
    float s = act ? (expf(v0 - m) + expf(v1 - m)) : 0.f;
#pragma unroll
    for (int off = 16; off > 0; off >>= 1)
        s += __shfl_xor_sync(0xFFFFFFFFu, s, off);
    float l = m + logf(s);
    if (act) {
        out[(size_t)i * OUTD + 2 * t]     = v0 - l;
        out[(size_t)i * OUTD + 2 * t + 1] = v1 - l;
    }
}

// ---------------- batchnorm stats ----------------
__global__ void __launch_bounds__(256) k_stats(const float* __restrict__ h) {
    int c = threadIdx.x;
    int rows_per_block = (NN + gridDim.x - 1) / gridDim.x;
    int r0 = blockIdx.x * rows_per_block;
    int r1 = min(NN, r0 + rows_per_block);
    float s = 0.f, ss = 0.f;
    for (int r = r0; r < r1; r++) {
        float v = h[(size_t)r * HIDD + c];
        s += v;
        ss = fmaf(v, v, ss);
    }
    atomicAdd(&g_sum[c], s);
    atomicAdd(&g_sumsq[c], ss);
}

__global__ void k_bn_finalize(const float* __restrict__ gamma,
                              const float* __restrict__ beta) {
    int c = threadIdx.x;
    float mu = g_sum[c] * (1.f / NN);
    float var = g_sumsq[c] * (1.f / NN) - mu * mu;
    float rstd = rsqrtf(var + BN_EPS);
    float sc = rstd * gamma[c];
    g_bn_s[c] = sc;
    g_bn_t[c] = beta[c] - mu * sc;
    g_sum[c] = 0.f;
    g_sumsq[c] = 0.f;
}

// ---------------- launch ----------------
extern "C" void kernel_launch(void* const* d_in, const int* in_sizes, int n_in,
                              void* d_out, int out_size) {
    const float* x     = (const float*)d_in[0];
    const void*  ei    = d_in[1];
    const float* W1    = (const float*)d_in[2];
    const float* b1    = (const float*)d_in[3];
    const float* W2    = (const float*)d_in[4];
    const float* b2    = (const float*)d_in[5];
    const float* W3    = (const float*)d_in[6];
    const float* b3    = (const float*)d_in[7];
    const float* gamma = (const float*)d_in[8];
    const float* beta  = (const float*)d_in[9];
    float* out = (float*)d_out;

    float *t1, *t2;
    __nv_bfloat16* xb;
    cudaGetSymbolAddress((void**)&t1, g_t1);
    cudaGetSymbolAddress((void**)&t2, g_t2);
    cudaGetSymbolAddress((void**)&xb, g_xb);
    __nv_bfloat16* t1b = reinterpret_cast<__nv_bfloat16*>(t1);

    // preprocessing (3 launches; xcast fused into convert grid)
    k_convert_deg_xcast<<<cdiv(XQ, 256), 256>>>(ei, x);   // 0
    k_scan_dinv<<<1, 1024>>>();                           // 1
    k_fill<<<cdiv(TOT, 256), 256>>>();                    // 2

    dim3 g256(4, cdiv(NN, 128));    // Ncols=256
    dim3 g40(1, cdiv(NN, 128));     // Ncols=40

    // layer 1: bf16-gather agg (x in bf16), GEMM fp32-out with fused bias
    k_agg_bf16<IND, 4, false><<<cdiv(NN, 4), 128>>>(xb, nullptr, t1);             // 3 <- profiled
    k_gemm_tc<false, true, false><<<g256, 256>>>(t1, W1, b1, t2, NN, IND, HIDD);  // 4
    k_stats<<<256, HIDD>>>(t2);                                                   // 5
    k_bn_finalize<<<1, HIDD>>>(gamma, beta);                                      // 6

    // layer 2: GEMM (BN+ReLU fused in) writes BF16; agg gathers bf16 -> fp32 t2
    k_gemm_tc<true, false, true><<<g256, 256>>>(t2, W2, nullptr, t1, NN, HIDD, HIDD); // 7
    k_agg_bf16<HIDD, 4, true><<<cdiv(NN, 4), 128>>>(t1b, b2, t2);                     // 8
    k_stats<<<256, HIDD>>>(t2);                                                        // 9
    k_bn_finalize<<<1, HIDD>>>(gamma, beta);                                           // 10

    // layer 3: GEMM writes bf16 logits; fused bf16 agg + log_softmax to output
    k_gemm_tc<true, false, true><<<g40, 256>>>(t2, W3, nullptr, t1, NN, HIDD, OUTD);   // 11
    k_agg_softmax_bf16<<<cdiv(NN, 4), 128>>>(t1b, b3, out);                            // 12
}